// round 14
// baseline (speedup 1.0000x reference)
#include <cuda_runtime.h>
#include <cstdint>

#define T_STEPS 200
#define HID     20
#define NTHR    128      // 4 warps; warp = gate-quarter (sub), lane = element
#define EPB     64       // elements per block (2 per thread: lane, lane+32)

typedef unsigned long long ULL;

// ---------- packed f32x2 helpers (Blackwell FFMA2; PTX-only) ----------
#define FMA2(d, a, b, c) \
    asm("fma.rn.f32x2 %0, %1, %2, %3;" : "=l"(d) : "l"(a), "l"(b), "l"(c))

__device__ __forceinline__ ULL pack2(float x, float y) {
    ULL r;
    asm("mov.b64 %0, {%1, %2};" : "=l"(r)
        : "r"(__float_as_uint(x)), "r"(__float_as_uint(y)));
    return r;
}
__device__ __forceinline__ void unpack2(ULL v, float &x, float &y) {
    unsigned lo, hi;
    asm("mov.b64 {%0, %1}, %2;" : "=r"(lo), "=r"(hi) : "l"(v));
    x = __uint_as_float(lo);
    y = __uint_as_float(hi);
}

// ---------- fast activations (MUFU EX2+RCP, ~1e-6 rel err) ----------
__device__ __forceinline__ float sigm(float x) {
    return __fdividef(1.0f, 1.0f + __expf(-x));
}
__device__ __forceinline__ float tanh_fast(float x) {
    float ax = fabsf(x);
    float e  = __expf(-2.0f * ax);
    float r  = __fdividef(1.0f - e, 1.0f + e);
    return copysignf(r, x);
}

// ---------- exact JAX threefry2x32 (20 rounds) ----------
__device__ __forceinline__ void threefry2x32(unsigned k0, unsigned k1,
                                             unsigned x0, unsigned x1,
                                             unsigned &o0, unsigned &o1) {
    unsigned ks2 = k0 ^ k1 ^ 0x1BD11BDAu;
    x0 += k0; x1 += k1;
#define TFR(r) { x0 += x1; x1 = (x1 << r) | (x1 >> (32 - r)); x1 ^= x0; }
    TFR(13) TFR(15) TFR(26) TFR(6)
    x0 += k1;  x1 += ks2 + 1u;
    TFR(17) TFR(29) TFR(16) TFR(24)
    x0 += ks2; x1 += k0 + 2u;
    TFR(13) TFR(15) TFR(26) TFR(6)
    x0 += k0;  x1 += k1 + 3u;
    TFR(17) TFR(29) TFR(16) TFR(24)
    x0 += k1;  x1 += ks2 + 4u;
    TFR(13) TFR(15) TFR(26) TFR(6)
    x0 += ks2; x1 += k0 + 5u;
#undef TFR
    o0 = x0; o1 = x1;
}
// JAX partitionable threefry: ctr=(0,j), bits = o0^o1  (key (0,42))
__device__ __forceinline__ unsigned jax_random_bits_partitionable(unsigned j) {
    unsigned o0, o1;
    threefry2x32(0u, 42u, 0u, j, o0, o1);
    return o0 ^ o1;
}

// One k-contribution for two elements: 5 broadcast LDS.128 -> 20 FFMA2.
// h arrives pre-duplicated as packed (h,h) from shared (no pack MOVs).
__device__ __forceinline__ void mv_accum2(ULL* gpa, ULL* gpb,
                                          ULL h2a, ULL h2b,
                                          const float4* __restrict__ wrow) {
    const ulonglong2* r = reinterpret_cast<const ulonglong2*>(wrow);
#pragma unroll
    for (int q = 0; q < 5; q++) {
        ulonglong2 w = r[q];
        FMA2(gpa[2 * q],     h2a, w.x, gpa[2 * q]);
        FMA2(gpa[2 * q + 1], h2a, w.y, gpa[2 * q + 1]);
        FMA2(gpb[2 * q],     h2b, w.x, gpb[2 * q]);
        FMA2(gpb[2 * q + 1], h2b, w.y, gpb[2 * q + 1]);
    }
}

// gp layout (units u0..u0+4): gp[2q],gp[2q+1] (q<4) = gate-group q for units
// (u0..u0+3); gp[8]=(i4,f4), gp[9]=(g4,o4) for unit u0+4
__device__ __forceinline__ void cell_update(ULL* gp, float* c, float* hout) {
    float iv[5], fv[5], gv[5], ov[5];
    unpack2(gp[0], iv[0], iv[1]); unpack2(gp[1], iv[2], iv[3]);
    unpack2(gp[2], fv[0], fv[1]); unpack2(gp[3], fv[2], fv[3]);
    unpack2(gp[4], gv[0], gv[1]); unpack2(gp[5], gv[2], gv[3]);
    unpack2(gp[6], ov[0], ov[1]); unpack2(gp[7], ov[2], ov[3]);
    unpack2(gp[8], iv[4], fv[4]);
    unpack2(gp[9], gv[4], ov[4]);
#pragma unroll
    for (int j = 0; j < 5; j++) {
        float cv = fmaf(sigm(fv[j]), c[j], sigm(iv[j]) * tanh_fast(gv[j]));
        c[j] = cv;
        hout[j] = sigm(ov[j]) * tanh_fast(cv);
    }
}

// dynamic shared layout (bytes)
#define OFF_SW    0                      // float4 [3][20][4][5]   = 19200
#define OFF_SWX   19200                  // float4 [2][4][5]       = 640
#define OFF_SBIAS 19840                  // float4 [2][4][5]       = 640
#define OFF_SHA   20480                  // ULL [2][20][64]        = 20480
#define OFF_SHB   40960                  // ULL [2][20][64]        = 20480
#define OFF_SLG   61440                  // float [3][4][64]       = 3072
#define SMEM_TOTAL 64512

__global__ void __launch_bounds__(NTHR, 2)
lstm_fused_kernel(const float* __restrict__ x,
                  const float* __restrict__ h0,
                  const float* __restrict__ c0,
                  const float* __restrict__ Wih0,
                  const float* __restrict__ Whh0,
                  const float* __restrict__ bih0,
                  const float* __restrict__ bhh0,
                  const float* __restrict__ Wih1,
                  const float* __restrict__ Whh1,
                  const float* __restrict__ bih1,
                  const float* __restrict__ bhh1,
                  const float* __restrict__ Wdec,
                  const float* __restrict__ bdec,
                  float* __restrict__ out,
                  int B) {
    extern __shared__ __align__(16) char dsm[];
    float4* sW    = reinterpret_cast<float4*>(dsm + OFF_SW);
    float4* sWx   = reinterpret_cast<float4*>(dsm + OFF_SWX);
    float4* sBias = reinterpret_cast<float4*>(dsm + OFF_SBIAS);
    ULL*    sHA   = reinterpret_cast<ULL*>(dsm + OFF_SHA);   // [buf][k][e] (h,h)
    ULL*    sHB   = reinterpret_cast<ULL*>(dsm + OFF_SHB);   // [buf][k][e] (h,h)
    float*  sLG   = reinterpret_cast<float*>(dsm + OFF_SLG); // [a][sub][e]

#define SW(m, k, s, q) sW[(((m) * HID + (k)) * 4 + (s)) * 5 + (q)]
#define SWX(i, s, q)   sWx[((i) * 4 + (s)) * 5 + (q)]
#define SBIAS(l, s, q) sBias[((l) * 4 + (s)) * 5 + (q)]
#define SHA(bf, k, e)  sHA[((bf) * HID + (k)) * EPB + (e)]
#define SHB(bf, k, e)  sHB[((bf) * HID + (k)) * EPB + (e)]
#define SLG(a, s, e)   sLG[((a) * 4 + (s)) * EPB + (e)]

    const int tid = threadIdx.x;
    const int sub = tid >> 5;           // warp id = gate quarter
    const int e0  = tid & 31;           // lane = first element
    const int e1  = e0 + 32;
    const int b0  = blockIdx.x * EPB + e0;
    const int b1  = b0 + 32;
    const int u0  = 5 * sub;

    // ---------------- stage weights ----------------
    {
        const float* Wsrc[3] = {Whh0, Wih1, Whh1};
        for (int idx = tid; idx < 3 * HID * 4 * 5; idx += NTHR) {
            int m = idx / (HID * 20);
            int r = idx % (HID * 20);
            int k = r / 20;
            int s = (r % 20) / 5;
            int q = r % 5;
            const float* W = Wsrc[m];
            float4 v;
            if (q < 4) {
                int g = 20 * q + 5 * s;
                v = make_float4(W[(g + 0) * HID + k], W[(g + 1) * HID + k],
                                W[(g + 2) * HID + k], W[(g + 3) * HID + k]);
            } else {
                int u = 5 * s + 4;
                v = make_float4(W[u * HID + k],        W[(20 + u) * HID + k],
                                W[(40 + u) * HID + k], W[(60 + u) * HID + k]);
            }
            SW(m, k, s, q) = v;
        }
        for (int idx = tid; idx < 2 * 4 * 5; idx += NTHR) {
            int i = idx / 20, s = (idx % 20) / 5, q = idx % 5;
            float4 v;
            if (q < 4) {
                int g = 20 * q + 5 * s;
                v = make_float4(Wih0[(g + 0) * 2 + i], Wih0[(g + 1) * 2 + i],
                                Wih0[(g + 2) * 2 + i], Wih0[(g + 3) * 2 + i]);
            } else {
                int u = 5 * s + 4;
                v = make_float4(Wih0[u * 2 + i],        Wih0[(20 + u) * 2 + i],
                                Wih0[(40 + u) * 2 + i], Wih0[(60 + u) * 2 + i]);
            }
            SWX(i, s, q) = v;
        }
        for (int idx = tid; idx < 2 * 4 * 5; idx += NTHR) {
            int l = idx / 20, s = (idx % 20) / 5, q = idx % 5;
            const float* bi = l ? bih1 : bih0;
            const float* bh = l ? bhh1 : bhh0;
            float4 v;
            if (q < 4) {
                int g = 20 * q + 5 * s;
                v = make_float4(bi[g] + bh[g],         bi[g + 1] + bh[g + 1],
                                bi[g + 2] + bh[g + 2], bi[g + 3] + bh[g + 3]);
            } else {
                int u = 5 * s + 4;
                v = make_float4(bi[u] + bh[u],           bi[20 + u] + bh[20 + u],
                                bi[40 + u] + bh[40 + u], bi[60 + u] + bh[60 + u]);
            }
            SBIAS(l, s, q) = v;
        }
    }

    // ---------------- init state ----------------
    // h1(s) lives in sHA[s&1]; h2(s) in sHB[s&1]. Initial states are step -1.
    float cA[2][5], cB[2][5], hA[2][5], hB[2][5];
#pragma unroll
    for (int j = 0; j < 5; j++) {
        int u = u0 + j;
        cA[0][j] = c0[(size_t)b0 * HID + u];
        cA[1][j] = c0[(size_t)b1 * HID + u];
        cB[0][j] = c0[(size_t)B * HID + (size_t)b0 * HID + u];
        cB[1][j] = c0[(size_t)B * HID + (size_t)b1 * HID + u];
        float a0 = h0[(size_t)b0 * HID + u];
        float a1 = h0[(size_t)b1 * HID + u];
        float v0 = h0[(size_t)B * HID + (size_t)b0 * HID + u];
        float v1 = h0[(size_t)B * HID + (size_t)b1 * HID + u];
        SHA(1, u, e0) = pack2(a0, a0);
        SHA(1, u, e1) = pack2(a1, a1);
        SHB(1, u, e0) = pack2(v0, v0);
        SHB(1, u, e1) = pack2(v1, v1);
    }
    __syncthreads();

    float lg[2][3] = {{0.f, 0.f, 0.f}, {0.f, 0.f, 0.f}};
    const float2* x2 = reinterpret_cast<const float2*>(x);
    float2 xv0 = x2[b0];
    float2 xv1 = x2[b1];

    // L1(t): reads sHA[(t-1)&1], writes h1(t) -> sHA[t&1]
#define L1_BODY(t) do {                                                        \
        const int wb = (t) & 1, rb = wb ^ 1;                                   \
        ULL gpa[10], gpb[10];                                                  \
        const ulonglong2* bb = (const ulonglong2*)&SBIAS(0, sub, 0);           \
        _Pragma("unroll")                                                      \
        for (int q = 0; q < 5; q++) {                                          \
            gpa[2 * q] = bb[q].x;  gpa[2 * q + 1] = bb[q].y;                   \
            gpb[2 * q] = bb[q].x;  gpb[2 * q + 1] = bb[q].y;                   \
        }                                                                      \
        mv_accum2(gpa, gpb, pack2(xv0.x, xv0.x), pack2(xv1.x, xv1.x),          \
                  &SWX(0, sub, 0));                                            \
        mv_accum2(gpa, gpb, pack2(xv0.y, xv0.y), pack2(xv1.y, xv1.y),          \
                  &SWX(1, sub, 0));                                            \
        _Pragma("unroll")                                                      \
        for (int k = 0; k < HID; k++)                                          \
            mv_accum2(gpa, gpb, SHA(rb, k, e0), SHA(rb, k, e1),                \
                      &SW(0, k, sub, 0));                                      \
        cell_update(gpa, cA[0], hA[0]);                                        \
        cell_update(gpb, cA[1], hA[1]);                                        \
        _Pragma("unroll")                                                      \
        for (int j = 0; j < 5; j++) {                                          \
            SHA(wb, u0 + j, e0) = pack2(hA[0][j], hA[0][j]);                   \
            SHA(wb, u0 + j, e1) = pack2(hA[1][j], hA[1][j]);                   \
        }                                                                      \
    } while (0)

    // L2(t): reads h1(t) from sHA[t&1], h2(t-1) from sHB[(t-1)&1];
    // writes h2(t) -> sHB[t&1]; accumulates decoder partials for step t.
#define L2_BODY(t) do {                                                        \
        const int hb = (t) & 1, rb2 = hb ^ 1;                                  \
        ULL g2a[10], g2b[10];                                                  \
        const ulonglong2* bb2 = (const ulonglong2*)&SBIAS(1, sub, 0);          \
        _Pragma("unroll")                                                      \
        for (int q = 0; q < 5; q++) {                                          \
            g2a[2 * q] = bb2[q].x;  g2a[2 * q + 1] = bb2[q].y;                 \
            g2b[2 * q] = bb2[q].x;  g2b[2 * q + 1] = bb2[q].y;                 \
        }                                                                      \
        _Pragma("unroll")                                                      \
        for (int k = 0; k < HID; k++)                                          \
            mv_accum2(g2a, g2b, SHA(hb, k, e0), SHA(hb, k, e1),                \
                      &SW(1, k, sub, 0));                                      \
        _Pragma("unroll")                                                      \
        for (int k = 0; k < HID; k++)                                          \
            mv_accum2(g2a, g2b, SHB(rb2, k, e0), SHB(rb2, k, e1),              \
                      &SW(2, k, sub, 0));                                      \
        cell_update(g2a, cB[0], hB[0]);                                        \
        cell_update(g2b, cB[1], hB[1]);                                        \
        _Pragma("unroll")                                                      \
        for (int j = 0; j < 5; j++) {                                          \
            SHB(hb, u0 + j, e0) = pack2(hB[0][j], hB[0][j]);                   \
            SHB(hb, u0 + j, e1) = pack2(hB[1][j], hB[1][j]);                   \
        }                                                                      \
        const float* wd = Wdec + (t) * HID + u0;                               \
        _Pragma("unroll")                                                      \
        for (int j = 0; j < 5; j++) {                                          \
            float w0 = __ldg(wd + j);                                          \
            float w1 = __ldg(wd + T_STEPS * HID + j);                          \
            float w2 = __ldg(wd + 2 * T_STEPS * HID + j);                      \
            lg[0][0] = fmaf(hB[0][j], w0, lg[0][0]);                           \
            lg[0][1] = fmaf(hB[0][j], w1, lg[0][1]);                           \
            lg[0][2] = fmaf(hB[0][j], w2, lg[0][2]);                           \
            lg[1][0] = fmaf(hB[1][j], w0, lg[1][0]);                           \
            lg[1][1] = fmaf(hB[1][j], w1, lg[1][1]);                           \
            lg[1][2] = fmaf(hB[1][j], w2, lg[1][2]);                           \
        }                                                                      \
    } while (0)

    // ---- software pipeline: iter i does L1(i) + L2(i-1); ONE barrier/iter ----
    L1_BODY(0);
    xv0 = x2[(size_t)B + b0];
    xv1 = x2[(size_t)B + b1];
    __syncthreads();

#pragma unroll 1
    for (int i = 1; i < T_STEPS; i++) {
        L1_BODY(i);
        L2_BODY(i - 1);
        {
            int tn = (i + 1 < T_STEPS) ? (i + 1) : i;
            xv0 = x2[(size_t)tn * B + b0];
            xv1 = x2[(size_t)tn * B + b1];
        }
        __syncthreads();
    }
    L2_BODY(T_STEPS - 1);

    // ---------------- outputs ----------------
    float* o_h = out + 2 * (size_t)B;
    float* o_c = o_h + 2 * (size_t)B * HID;
#pragma unroll
    for (int j = 0; j < 5; j++) {
        int u = u0 + j;
        o_h[(size_t)b0 * HID + u]                   = hA[0][j];
        o_h[(size_t)b1 * HID + u]                   = hA[1][j];
        o_h[(size_t)B * HID + (size_t)b0 * HID + u] = hB[0][j];
        o_h[(size_t)B * HID + (size_t)b1 * HID + u] = hB[1][j];
        o_c[(size_t)b0 * HID + u]                   = cA[0][j];
        o_c[(size_t)b1 * HID + u]                   = cA[1][j];
        o_c[(size_t)B * HID + (size_t)b0 * HID + u] = cB[0][j];
        o_c[(size_t)B * HID + (size_t)b1 * HID + u] = cB[1][j];
    }

    // reduce decoder partials across the 4 warps
#pragma unroll
    for (int a = 0; a < 3; a++) {
        SLG(a, sub, e0) = lg[0][a];
        SLG(a, sub, e1) = lg[1][a];
    }
    __syncthreads();

    if (sub == 0) {
#pragma unroll
        for (int ei = 0; ei < 2; ei++) {
            int e = (ei == 0) ? e0 : e1;
            int b = (ei == 0) ? b0 : b1;
            float logit0 = SLG(0, 0, e) + SLG(0, 1, e) + SLG(0, 2, e) + SLG(0, 3, e) + bdec[0];
            float logit1 = SLG(1, 0, e) + SLG(1, 1, e) + SLG(1, 2, e) + SLG(1, 3, e) + bdec[1];
            float logit2 = SLG(2, 0, e) + SLG(2, 1, e) + SLG(2, 2, e) + SLG(2, 3, e) + bdec[2];

            float m   = fmaxf(logit0, fmaxf(logit1, logit2));
            float lse = m + logf(expf(logit0 - m) + expf(logit1 - m) + expf(logit2 - m));

            const float tinyf = 1.17549435e-38f;
            float best = -1e30f, sel_logit = logit0;
            int act = 0;
#pragma unroll
            for (int a = 0; a < 3; a++) {
                unsigned bits = jax_random_bits_partitionable((unsigned)(b * 3 + a));
                float f  = __uint_as_float((bits >> 9) | 0x3f800000u) - 1.0f;
                float uu = fmaxf(tinyf, f + tinyf);
                float gmb = -logf(-logf(uu));
                float lgv = (a == 0) ? logit0 : (a == 1) ? logit1 : logit2;
                float v   = lgv + gmb;
                if (v > best) { best = v; act = a; sel_logit = lgv; }
            }
            out[b]     = (float)act;
            out[B + b] = sel_logit - lse;
        }
    }
}

extern "C" void kernel_launch(void* const* d_in, const int* in_sizes, int n_in,
                              void* d_out, int out_size) {
    const float* x    = (const float*)d_in[0];
    const float* h0   = (const float*)d_in[1];
    const float* c0   = (const float*)d_in[2];
    const float* Wih0 = (const float*)d_in[3];
    const float* Whh0 = (const float*)d_in[4];
    const float* bih0 = (const float*)d_in[5];
    const float* bhh0 = (const float*)d_in[6];
    const float* Wih1 = (const float*)d_in[7];
    const float* Whh1 = (const float*)d_in[8];
    const float* bih1 = (const float*)d_in[9];
    const float* bhh1 = (const float*)d_in[10];
    const float* Wdec = (const float*)d_in[11];
    const float* bdec = (const float*)d_in[12];

    int B = in_sizes[0] / (T_STEPS * 2);   // x is [T, B, 2]

    cudaFuncSetAttribute(lstm_fused_kernel,
                         cudaFuncAttributeMaxDynamicSharedMemorySize, SMEM_TOTAL);

    dim3 grid(B / EPB), block(NTHR);
    lstm_fused_kernel<<<grid, block, SMEM_TOTAL>>>(
        x, h0, c0, Wih0, Whh0, bih0, bhh0,
        Wih1, Whh1, bih1, bhh1, Wdec, bdec,
        (float*)d_out, B);
}

// round 15
// speedup vs baseline: 1.0584x; 1.0584x over previous
#include <cuda_runtime.h>
#include <cstdint>

#define T_STEPS 200
#define HID     20
#define NTHR    128      // 4 warps; warp = gate-quarter (sub), lane = element
#define EPB     64       // elements per block (2 per thread: lane, lane+32)

typedef unsigned long long ULL;

// ---------- packed f32x2 helpers (Blackwell FFMA2; PTX-only) ----------
#define FMA2(d, a, b, c) \
    asm("fma.rn.f32x2 %0, %1, %2, %3;" : "=l"(d) : "l"(a), "l"(b), "l"(c))

__device__ __forceinline__ ULL pack2(float x, float y) {
    ULL r;
    asm("mov.b64 %0, {%1, %2};" : "=l"(r)
        : "r"(__float_as_uint(x)), "r"(__float_as_uint(y)));
    return r;
}
__device__ __forceinline__ void unpack2(ULL v, float &x, float &y) {
    unsigned lo, hi;
    asm("mov.b64 {%0, %1}, %2;" : "=r"(lo), "=r"(hi) : "l"(v));
    x = __uint_as_float(lo);
    y = __uint_as_float(hi);
}

// ---------- fast activations (MUFU EX2+RCP, ~1e-6 rel err) ----------
__device__ __forceinline__ float sigm(float x) {
    return __fdividef(1.0f, 1.0f + __expf(-x));
}
__device__ __forceinline__ float tanh_fast(float x) {
    float ax = fabsf(x);
    float e  = __expf(-2.0f * ax);
    float r  = __fdividef(1.0f - e, 1.0f + e);
    return copysignf(r, x);
}

// ---------- exact JAX threefry2x32 (20 rounds) ----------
__device__ __forceinline__ void threefry2x32(unsigned k0, unsigned k1,
                                             unsigned x0, unsigned x1,
                                             unsigned &o0, unsigned &o1) {
    unsigned ks2 = k0 ^ k1 ^ 0x1BD11BDAu;
    x0 += k0; x1 += k1;
#define TFR(r) { x0 += x1; x1 = (x1 << r) | (x1 >> (32 - r)); x1 ^= x0; }
    TFR(13) TFR(15) TFR(26) TFR(6)
    x0 += k1;  x1 += ks2 + 1u;
    TFR(17) TFR(29) TFR(16) TFR(24)
    x0 += ks2; x1 += k0 + 2u;
    TFR(13) TFR(15) TFR(26) TFR(6)
    x0 += k0;  x1 += k1 + 3u;
    TFR(17) TFR(29) TFR(16) TFR(24)
    x0 += k1;  x1 += ks2 + 4u;
    TFR(13) TFR(15) TFR(26) TFR(6)
    x0 += ks2; x1 += k0 + 5u;
#undef TFR
    o0 = x0; o1 = x1;
}
// JAX partitionable threefry: ctr=(0,j), bits = o0^o1  (key (0,42))
__device__ __forceinline__ unsigned jax_random_bits_partitionable(unsigned j) {
    unsigned o0, o1;
    threefry2x32(0u, 42u, 0u, j, o0, o1);
    return o0 ^ o1;
}

// One k-contribution for two elements: 5 broadcast LDS.128 -> 20 FFMA2.
// h arrives pre-duplicated as packed (h,h) from shared (no pack MOVs).
__device__ __forceinline__ void mv_accum2(ULL* gpa, ULL* gpb,
                                          ULL h2a, ULL h2b,
                                          const float4* __restrict__ wrow) {
    const ulonglong2* r = reinterpret_cast<const ulonglong2*>(wrow);
#pragma unroll
    for (int q = 0; q < 5; q++) {
        ulonglong2 w = r[q];
        FMA2(gpa[2 * q],     h2a, w.x, gpa[2 * q]);
        FMA2(gpa[2 * q + 1], h2a, w.y, gpa[2 * q + 1]);
        FMA2(gpb[2 * q],     h2b, w.x, gpb[2 * q]);
        FMA2(gpb[2 * q + 1], h2b, w.y, gpb[2 * q + 1]);
    }
}

// gp layout (units u0..u0+4): gp[2q],gp[2q+1] (q<4) = gate-group q for units
// (u0..u0+3); gp[8]=(i4,f4), gp[9]=(g4,o4) for unit u0+4
__device__ __forceinline__ void cell_update(ULL* gp, float* c, float* hout) {
    float iv[5], fv[5], gv[5], ov[5];
    unpack2(gp[0], iv[0], iv[1]); unpack2(gp[1], iv[2], iv[3]);
    unpack2(gp[2], fv[0], fv[1]); unpack2(gp[3], fv[2], fv[3]);
    unpack2(gp[4], gv[0], gv[1]); unpack2(gp[5], gv[2], gv[3]);
    unpack2(gp[6], ov[0], ov[1]); unpack2(gp[7], ov[2], ov[3]);
    unpack2(gp[8], iv[4], fv[4]);
    unpack2(gp[9], gv[4], ov[4]);
#pragma unroll
    for (int j = 0; j < 5; j++) {
        float cv = fmaf(sigm(fv[j]), c[j], sigm(iv[j]) * tanh_fast(gv[j]));
        c[j] = cv;
        hout[j] = sigm(ov[j]) * tanh_fast(cv);
    }
}

// dynamic shared layout (bytes)
#define OFF_SW    0                      // float4 [3][20][4][5]   = 19200
#define OFF_SWX   19200                  // float4 [2][4][5]       = 640
#define OFF_SBIAS 19840                  // float4 [2][4][5]       = 640
#define OFF_SHA   20480                  // ULL [2][20][64]        = 20480
#define OFF_SHB   40960                  // ULL [2][20][64]        = 20480
#define OFF_SLG   61440                  // float [3][4][64]       = 3072
#define SMEM_TOTAL 64512

__global__ void __launch_bounds__(NTHR, 2)
lstm_fused_kernel(const float* __restrict__ x,
                  const float* __restrict__ h0,
                  const float* __restrict__ c0,
                  const float* __restrict__ Wih0,
                  const float* __restrict__ Whh0,
                  const float* __restrict__ bih0,
                  const float* __restrict__ bhh0,
                  const float* __restrict__ Wih1,
                  const float* __restrict__ Whh1,
                  const float* __restrict__ bih1,
                  const float* __restrict__ bhh1,
                  const float* __restrict__ Wdec,
                  const float* __restrict__ bdec,
                  float* __restrict__ out,
                  int B) {
    extern __shared__ __align__(16) char dsm[];
    float4* sW    = reinterpret_cast<float4*>(dsm + OFF_SW);
    float4* sWx   = reinterpret_cast<float4*>(dsm + OFF_SWX);
    float4* sBias = reinterpret_cast<float4*>(dsm + OFF_SBIAS);
    ULL*    sHA   = reinterpret_cast<ULL*>(dsm + OFF_SHA);   // [buf][k][e] (h,h)
    ULL*    sHB   = reinterpret_cast<ULL*>(dsm + OFF_SHB);   // [buf][k][e] (h,h)
    float*  sLG   = reinterpret_cast<float*>(dsm + OFF_SLG); // [a][sub][e]

#define SW(m, k, s, q) sW[(((m) * HID + (k)) * 4 + (s)) * 5 + (q)]
#define SWX(i, s, q)   sWx[((i) * 4 + (s)) * 5 + (q)]
#define SBIAS(l, s, q) sBias[((l) * 4 + (s)) * 5 + (q)]
#define SHA(bf, k, e)  sHA[((bf) * HID + (k)) * EPB + (e)]
#define SHB(bf, k, e)  sHB[((bf) * HID + (k)) * EPB + (e)]
#define SLG(a, s, e)   sLG[((a) * 4 + (s)) * EPB + (e)]

    const int tid = threadIdx.x;
    const int sub = tid >> 5;           // warp id = gate quarter
    const int e0  = tid & 31;           // lane = first element
    const int e1  = e0 + 32;
    const int b0  = blockIdx.x * EPB + e0;
    const int b1  = b0 + 32;
    const int u0  = 5 * sub;

    // ---------------- stage weights ----------------
    {
        const float* Wsrc[3] = {Whh0, Wih1, Whh1};
        for (int idx = tid; idx < 3 * HID * 4 * 5; idx += NTHR) {
            int m = idx / (HID * 20);
            int r = idx % (HID * 20);
            int k = r / 20;
            int s = (r % 20) / 5;
            int q = r % 5;
            const float* W = Wsrc[m];
            float4 v;
            if (q < 4) {
                int g = 20 * q + 5 * s;
                v = make_float4(W[(g + 0) * HID + k], W[(g + 1) * HID + k],
                                W[(g + 2) * HID + k], W[(g + 3) * HID + k]);
            } else {
                int u = 5 * s + 4;
                v = make_float4(W[u * HID + k],        W[(20 + u) * HID + k],
                                W[(40 + u) * HID + k], W[(60 + u) * HID + k]);
            }
            SW(m, k, s, q) = v;
        }
        for (int idx = tid; idx < 2 * 4 * 5; idx += NTHR) {
            int i = idx / 20, s = (idx % 20) / 5, q = idx % 5;
            float4 v;
            if (q < 4) {
                int g = 20 * q + 5 * s;
                v = make_float4(Wih0[(g + 0) * 2 + i], Wih0[(g + 1) * 2 + i],
                                Wih0[(g + 2) * 2 + i], Wih0[(g + 3) * 2 + i]);
            } else {
                int u = 5 * s + 4;
                v = make_float4(Wih0[u * 2 + i],        Wih0[(20 + u) * 2 + i],
                                Wih0[(40 + u) * 2 + i], Wih0[(60 + u) * 2 + i]);
            }
            SWX(i, s, q) = v;
        }
        for (int idx = tid; idx < 2 * 4 * 5; idx += NTHR) {
            int l = idx / 20, s = (idx % 20) / 5, q = idx % 5;
            const float* bi = l ? bih1 : bih0;
            const float* bh = l ? bhh1 : bhh0;
            float4 v;
            if (q < 4) {
                int g = 20 * q + 5 * s;
                v = make_float4(bi[g] + bh[g],         bi[g + 1] + bh[g + 1],
                                bi[g + 2] + bh[g + 2], bi[g + 3] + bh[g + 3]);
            } else {
                int u = 5 * s + 4;
                v = make_float4(bi[u] + bh[u],           bi[20 + u] + bh[20 + u],
                                bi[40 + u] + bh[40 + u], bi[60 + u] + bh[60 + u]);
            }
            SBIAS(l, s, q) = v;
        }
    }

    // ---------------- init state ----------------
    // h1(s) lives in sHA[s&1]; h2(s) in sHB[s&1]. Initial states are step -1.
    float cA[2][5], cB[2][5], hA[2][5], hB[2][5];
#pragma unroll
    for (int j = 0; j < 5; j++) {
        int u = u0 + j;
        cA[0][j] = c0[(size_t)b0 * HID + u];
        cA[1][j] = c0[(size_t)b1 * HID + u];
        cB[0][j] = c0[(size_t)B * HID + (size_t)b0 * HID + u];
        cB[1][j] = c0[(size_t)B * HID + (size_t)b1 * HID + u];
        float a0 = h0[(size_t)b0 * HID + u];
        float a1 = h0[(size_t)b1 * HID + u];
        float v0 = h0[(size_t)B * HID + (size_t)b0 * HID + u];
        float v1 = h0[(size_t)B * HID + (size_t)b1 * HID + u];
        SHA(1, u, e0) = pack2(a0, a0);
        SHA(1, u, e1) = pack2(a1, a1);
        SHB(1, u, e0) = pack2(v0, v0);
        SHB(1, u, e1) = pack2(v1, v1);
    }
    __syncthreads();

    float lg[2][3] = {{0.f, 0.f, 0.f}, {0.f, 0.f, 0.f}};
    const float2* x2 = reinterpret_cast<const float2*>(x);
    float2 xv0 = x2[b0];
    float2 xv1 = x2[b1];

    // L1(t): reads sHA[(t-1)&1], writes h1(t) -> sHA[t&1]
#define L1_BODY(t) do {                                                        \
        const int wb = (t) & 1, rb = wb ^ 1;                                   \
        ULL gpa[10], gpb[10];                                                  \
        const ulonglong2* bb = (const ulonglong2*)&SBIAS(0, sub, 0);           \
        _Pragma("unroll")                                                      \
        for (int q = 0; q < 5; q++) {                                          \
            gpa[2 * q] = bb[q].x;  gpa[2 * q + 1] = bb[q].y;                   \
            gpb[2 * q] = bb[q].x;  gpb[2 * q + 1] = bb[q].y;                   \
        }                                                                      \
        mv_accum2(gpa, gpb, pack2(xv0.x, xv0.x), pack2(xv1.x, xv1.x),          \
                  &SWX(0, sub, 0));                                            \
        mv_accum2(gpa, gpb, pack2(xv0.y, xv0.y), pack2(xv1.y, xv1.y),          \
                  &SWX(1, sub, 0));                                            \
        _Pragma("unroll")                                                      \
        for (int k = 0; k < HID; k++)                                          \
            mv_accum2(gpa, gpb, SHA(rb, k, e0), SHA(rb, k, e1),                \
                      &SW(0, k, sub, 0));                                      \
        cell_update(gpa, cA[0], hA[0]);                                        \
        cell_update(gpb, cA[1], hA[1]);                                        \
        _Pragma("unroll")                                                      \
        for (int j = 0; j < 5; j++) {                                          \
            SHA(wb, u0 + j, e0) = pack2(hA[0][j], hA[0][j]);                   \
            SHA(wb, u0 + j, e1) = pack2(hA[1][j], hA[1][j]);                   \
        }                                                                      \
    } while (0)

    // L2(t): reads h1(t) from sHA[t&1], h2(t-1) from sHB[(t-1)&1];
    // writes h2(t) -> sHB[t&1]; accumulates decoder partials for step t.
#define L2_BODY(t) do {                                                        \
        const int hb = (t) & 1, rb2 = hb ^ 1;                                  \
        ULL g2a[10], g2b[10];                                                  \
        const ulonglong2* bb2 = (const ulonglong2*)&SBIAS(1, sub, 0);          \
        _Pragma("unroll")                                                      \
        for (int q = 0; q < 5; q++) {                                          \
            g2a[2 * q] = bb2[q].x;  g2a[2 * q + 1] = bb2[q].y;                 \
            g2b[2 * q] = bb2[q].x;  g2b[2 * q + 1] = bb2[q].y;                 \
        }                                                                      \
        _Pragma("unroll")                                                      \
        for (int k = 0; k < HID; k++)                                          \
            mv_accum2(g2a, g2b, SHA(hb, k, e0), SHA(hb, k, e1),                \
                      &SW(1, k, sub, 0));                                      \
        _Pragma("unroll")                                                      \
        for (int k = 0; k < HID; k++)                                          \
            mv_accum2(g2a, g2b, SHB(rb2, k, e0), SHB(rb2, k, e1),              \
                      &SW(2, k, sub, 0));                                      \
        cell_update(g2a, cB[0], hB[0]);                                        \
        cell_update(g2b, cB[1], hB[1]);                                        \
        _Pragma("unroll")                                                      \
        for (int j = 0; j < 5; j++) {                                          \
            SHB(hb, u0 + j, e0) = pack2(hB[0][j], hB[0][j]);                   \
            SHB(hb, u0 + j, e1) = pack2(hB[1][j], hB[1][j]);                   \
        }                                                                      \
        const float* wd = Wdec + (t) * HID + u0;                               \
        _Pragma("unroll")                                                      \
        for (int j = 0; j < 5; j++) {                                          \
            float w0 = __ldg(wd + j);                                          \
            float w1 = __ldg(wd + T_STEPS * HID + j);                          \
            float w2 = __ldg(wd + 2 * T_STEPS * HID + j);                      \
            lg[0][0] = fmaf(hB[0][j], w0, lg[0][0]);                           \
            lg[0][1] = fmaf(hB[0][j], w1, lg[0][1]);                           \
            lg[0][2] = fmaf(hB[0][j], w2, lg[0][2]);                           \
            lg[1][0] = fmaf(hB[1][j], w0, lg[1][0]);                           \
            lg[1][1] = fmaf(hB[1][j], w1, lg[1][1]);                           \
            lg[1][2] = fmaf(hB[1][j], w2, lg[1][2]);                           \
        }                                                                      \
    } while (0)

    // ---- software pipeline: iter i does L1(i) + L2(i-1); ONE barrier/iter ----
    L1_BODY(0);
    xv0 = x2[(size_t)B + b0];
    xv1 = x2[(size_t)B + b1];
    __syncthreads();

#pragma unroll 1
    for (int i = 1; i < T_STEPS; i++) {
        L1_BODY(i);
        L2_BODY(i - 1);
        {
            int tn = (i + 1 < T_STEPS) ? (i + 1) : i;
            xv0 = x2[(size_t)tn * B + b0];
            xv1 = x2[(size_t)tn * B + b1];
        }
        __syncthreads();
    }
    L2_BODY(T_STEPS - 1);

    // ---------------- outputs ----------------
    float* o_h = out + 2 * (size_t)B;
    float* o_c = o_h + 2 * (size_t)B * HID;
#pragma unroll
    for (int j = 0; j < 5; j++) {
        int u = u0 + j;
        o_h[(size_t)b0 * HID + u]                   = hA[0][j];
        o_h[(size_t)b1 * HID + u]                   = hA[1][j];
        o_h[(size_t)B * HID + (size_t)b0 * HID + u] = hB[0][j];
        o_h[(size_t)B * HID + (size_t)b1 * HID + u] = hB[1][j];
        o_c[(size_t)b0 * HID + u]                   = cA[0][j];
        o_c[(size_t)b1 * HID + u]                   = cA[1][j];
        o_c[(size_t)B * HID + (size_t)b0 * HID + u] = cB[0][j];
        o_c[(size_t)B * HID + (size_t)b1 * HID + u] = cB[1][j];
    }

    // reduce decoder partials across the 4 warps
#pragma unroll
    for (int a = 0; a < 3; a++) {
        SLG(a, sub, e0) = lg[0][a];
        SLG(a, sub, e1) = lg[1][a];
    }
    __syncthreads();

    if (sub == 0) {
#pragma unroll
        for (int ei = 0; ei < 2; ei++) {
            int e = (ei == 0) ? e0 : e1;
            int b = (ei == 0) ? b0 : b1;
            float logit0 = SLG(0, 0, e) + SLG(0, 1, e) + SLG(0, 2, e) + SLG(0, 3, e) + bdec[0];
            float logit1 = SLG(1, 0, e) + SLG(1, 1, e) + SLG(1, 2, e) + SLG(1, 3, e) + bdec[1];
            float logit2 = SLG(2, 0, e) + SLG(2, 1, e) + SLG(2, 2, e) + SLG(2, 3, e) + bdec[2];

            float m   = fmaxf(logit0, fmaxf(logit1, logit2));
            float lse = m + logf(expf(logit0 - m) + expf(logit1 - m) + expf(logit2 - m));

            const float tinyf = 1.17549435e-38f;
            float best = -1e30f, sel_logit = logit0;
            int act = 0;
#pragma unroll
            for (int a = 0; a < 3; a++) {
                unsigned bits = jax_random_bits_partitionable((unsigned)(b * 3 + a));
                float f  = __uint_as_float((bits >> 9) | 0x3f800000u) - 1.0f;
                float uu = fmaxf(tinyf, f + tinyf);
                float gmb = -logf(-logf(uu));
                float lgv = (a == 0) ? logit0 : (a == 1) ? logit1 : logit2;
                float v   = lgv + gmb;
                if (v > best) { best = v; act = a; sel_logit = lgv; }
            }
            out[b]     = (float)act;
            out[B + b] = sel_logit - lse;
        }
    }
}

extern "C" void kernel_launch(void* const* d_in, const int* in_sizes, int n_in,
                              void* d_out, int out_size) {
    const float* x    = (const float*)d_in[0];
    const float* h0   = (const float*)d_in[1];
    const float* c0   = (const float*)d_in[2];
    const float* Wih0 = (const float*)d_in[3];
    const float* Whh0 = (const float*)d_in[4];
    const float* bih0 = (const float*)d_in[5];
    const float* bhh0 = (const float*)d_in[6];
    const float* Wih1 = (const float*)d_in[7];
    const float* Whh1 = (const float*)d_in[8];
    const float* bih1 = (const float*)d_in[9];
    const float* bhh1 = (const float*)d_in[10];
    const float* Wdec = (const float*)d_in[11];
    const float* bdec = (const float*)d_in[12];

    int B = in_sizes[0] / (T_STEPS * 2);   // x is [T, B, 2]

    cudaFuncSetAttribute(lstm_fused_kernel,
                         cudaFuncAttributeMaxDynamicSharedMemorySize, SMEM_TOTAL);

    dim3 grid(B / EPB), block(NTHR);
    lstm_fused_kernel<<<grid, block, SMEM_TOTAL>>>(
        x, h0, c0, Wih0, Whh0, bih0, bhh0,
        Wih1, Whh1, bih1, bhh1, Wdec, bdec,
        (float*)d_out, B);
}

// round 16
// speedup vs baseline: 1.1389x; 1.0760x over previous
#include <cuda_runtime.h>
#include <cstdint>

#define T_STEPS 200
#define HID     20
#define NTHR    128      // 4 warps; warp = gate-quarter (sub), lane = element
#define EPB     64       // elements per block (2 per thread: lane, lane+32)
#define HPAD    21       // padded hidden stride (coprime with 32 -> conflict-free)

typedef unsigned long long ULL;

// ---------- packed f32x2 helpers (Blackwell FFMA2; PTX-only) ----------
#define FMA2(d, a, b, c) \
    asm("fma.rn.f32x2 %0, %1, %2, %3;" : "=l"(d) : "l"(a), "l"(b), "l"(c))

__device__ __forceinline__ ULL pack2(float x, float y) {
    ULL r;
    asm("mov.b64 %0, {%1, %2};" : "=l"(r)
        : "r"(__float_as_uint(x)), "r"(__float_as_uint(y)));
    return r;
}
__device__ __forceinline__ void unpack2(ULL v, float &x, float &y) {
    unsigned lo, hi;
    asm("mov.b64 {%0, %1}, %2;" : "=r"(lo), "=r"(hi) : "l"(v));
    x = __uint_as_float(lo);
    y = __uint_as_float(hi);
}

// ---------- fast activations (MUFU EX2+RCP, ~1e-6 rel err) ----------
__device__ __forceinline__ float sigm(float x) {
    return __fdividef(1.0f, 1.0f + __expf(-x));
}
__device__ __forceinline__ float tanh_fast(float x) {
    float ax = fabsf(x);
    float e  = __expf(-2.0f * ax);
    float r  = __fdividef(1.0f - e, 1.0f + e);
    return copysignf(r, x);
}

// ---------- exact JAX threefry2x32 (20 rounds) ----------
__device__ __forceinline__ void threefry2x32(unsigned k0, unsigned k1,
                                             unsigned x0, unsigned x1,
                                             unsigned &o0, unsigned &o1) {
    unsigned ks2 = k0 ^ k1 ^ 0x1BD11BDAu;
    x0 += k0; x1 += k1;
#define TFR(r) { x0 += x1; x1 = (x1 << r) | (x1 >> (32 - r)); x1 ^= x0; }
    TFR(13) TFR(15) TFR(26) TFR(6)
    x0 += k1;  x1 += ks2 + 1u;
    TFR(17) TFR(29) TFR(16) TFR(24)
    x0 += ks2; x1 += k0 + 2u;
    TFR(13) TFR(15) TFR(26) TFR(6)
    x0 += k0;  x1 += k1 + 3u;
    TFR(17) TFR(29) TFR(16) TFR(24)
    x0 += k1;  x1 += ks2 + 4u;
    TFR(13) TFR(15) TFR(26) TFR(6)
    x0 += ks2; x1 += k0 + 5u;
#undef TFR
    o0 = x0; o1 = x1;
}
// JAX partitionable threefry: ctr=(0,j), bits = o0^o1  (key (0,42))
__device__ __forceinline__ unsigned jax_random_bits_partitionable(unsigned j) {
    unsigned o0, o1;
    threefry2x32(0u, 42u, 0u, j, o0, o1);
    return o0 ^ o1;
}

// One k-contribution for two elements: 5 broadcast LDS.128 -> 20 FFMA2.
__device__ __forceinline__ void mv_accum2(ULL* gpa, ULL* gpb,
                                          float ha, float hb,
                                          const float4* __restrict__ wrow) {
    ULL h2a = pack2(ha, ha);
    ULL h2b = pack2(hb, hb);
    const ulonglong2* r = reinterpret_cast<const ulonglong2*>(wrow);
#pragma unroll
    for (int q = 0; q < 5; q++) {
        ulonglong2 w = r[q];
        FMA2(gpa[2 * q],     h2a, w.x, gpa[2 * q]);
        FMA2(gpa[2 * q + 1], h2a, w.y, gpa[2 * q + 1]);
        FMA2(gpb[2 * q],     h2b, w.x, gpb[2 * q]);
        FMA2(gpb[2 * q + 1], h2b, w.y, gpb[2 * q + 1]);
    }
}

// gp layout (units u0..u0+4): gp[2q],gp[2q+1] (q<4) = gate-group q for units
// (u0..u0+3); gp[8]=(i4,f4), gp[9]=(g4,o4) for unit u0+4
__device__ __forceinline__ void cell_update(ULL* gp, float* c, float* hout) {
    float iv[5], fv[5], gv[5], ov[5];
    unpack2(gp[0], iv[0], iv[1]); unpack2(gp[1], iv[2], iv[3]);
    unpack2(gp[2], fv[0], fv[1]); unpack2(gp[3], fv[2], fv[3]);
    unpack2(gp[4], gv[0], gv[1]); unpack2(gp[5], gv[2], gv[3]);
    unpack2(gp[6], ov[0], ov[1]); unpack2(gp[7], ov[2], ov[3]);
    unpack2(gp[8], iv[4], fv[4]);
    unpack2(gp[9], gv[4], ov[4]);
#pragma unroll
    for (int j = 0; j < 5; j++) {
        float cv = fmaf(sigm(fv[j]), c[j], sigm(iv[j]) * tanh_fast(gv[j]));
        c[j] = cv;
        hout[j] = sigm(ov[j]) * tanh_fast(cv);
    }
}

__global__ void __launch_bounds__(NTHR, 2)
lstm_fused_kernel(const float* __restrict__ x,
                  const float* __restrict__ h0,
                  const float* __restrict__ c0,
                  const float* __restrict__ Wih0,
                  const float* __restrict__ Whh0,
                  const float* __restrict__ bih0,
                  const float* __restrict__ bhh0,
                  const float* __restrict__ Wih1,
                  const float* __restrict__ Whh1,
                  const float* __restrict__ bih1,
                  const float* __restrict__ bhh1,
                  const float* __restrict__ Wdec,
                  const float* __restrict__ bdec,
                  float* __restrict__ out,
                  int B) {
    // sW[m][k][sub][q]: m=0 Whh0, m=1 Wih1, m=2 Whh1 (gate-permuted float4 packs)
    __shared__ float4 sW[3][HID][4][5];
    __shared__ float4 sWx[2][4][5];        // Wih0 columns 0/1
    __shared__ float4 sBias[2][4][5];      // combined biases per layer
    __shared__ float  sHA[2][EPB][HPAD];   // double-buffered layer-1 h (scalar)
    __shared__ float  sHB[2][EPB][HPAD];   // double-buffered layer-2 h (scalar)
    __shared__ float  sLG[3][4][EPB];      // decoder partial reduction scratch

    const int tid = threadIdx.x;
    const int sub = tid >> 5;           // warp id = gate quarter
    const int e0  = tid & 31;           // lane = first element
    const int e1  = e0 + 32;            // second element
    const int b0  = blockIdx.x * EPB + e0;
    const int b1  = b0 + 32;
    const int u0  = 5 * sub;

    // ---------------- stage weights ----------------
    {
        const float* Wsrc[3] = {Whh0, Wih1, Whh1};
        for (int idx = tid; idx < 3 * HID * 4 * 5; idx += NTHR) {
            int m = idx / (HID * 20);
            int r = idx % (HID * 20);
            int k = r / 20;
            int s = (r % 20) / 5;
            int q = r % 5;
            const float* W = Wsrc[m];
            float4 v;
            if (q < 4) {
                int g = 20 * q + 5 * s;
                v = make_float4(W[(g + 0) * HID + k], W[(g + 1) * HID + k],
                                W[(g + 2) * HID + k], W[(g + 3) * HID + k]);
            } else {
                int u = 5 * s + 4;
                v = make_float4(W[u * HID + k],        W[(20 + u) * HID + k],
                                W[(40 + u) * HID + k], W[(60 + u) * HID + k]);
            }
            sW[m][k][s][q] = v;
        }
        for (int idx = tid; idx < 2 * 4 * 5; idx += NTHR) {
            int i = idx / 20, s = (idx % 20) / 5, q = idx % 5;
            float4 v;
            if (q < 4) {
                int g = 20 * q + 5 * s;
                v = make_float4(Wih0[(g + 0) * 2 + i], Wih0[(g + 1) * 2 + i],
                                Wih0[(g + 2) * 2 + i], Wih0[(g + 3) * 2 + i]);
            } else {
                int u = 5 * s + 4;
                v = make_float4(Wih0[u * 2 + i],        Wih0[(20 + u) * 2 + i],
                                Wih0[(40 + u) * 2 + i], Wih0[(60 + u) * 2 + i]);
            }
            sWx[i][s][q] = v;
        }
        for (int idx = tid; idx < 2 * 4 * 5; idx += NTHR) {
            int l = idx / 20, s = (idx % 20) / 5, q = idx % 5;
            const float* bi = l ? bih1 : bih0;
            const float* bh = l ? bhh1 : bhh0;
            float4 v;
            if (q < 4) {
                int g = 20 * q + 5 * s;
                v = make_float4(bi[g] + bh[g],         bi[g + 1] + bh[g + 1],
                                bi[g + 2] + bh[g + 2], bi[g + 3] + bh[g + 3]);
            } else {
                int u = 5 * s + 4;
                v = make_float4(bi[u] + bh[u],           bi[20 + u] + bh[20 + u],
                                bi[40 + u] + bh[40 + u], bi[60 + u] + bh[60 + u]);
            }
            sBias[l][s][q] = v;
        }
    }

    // ---------------- init state ----------------
    // h1(s) lives in sHA[s&1]; h2(s) in sHB[s&1]. Initial states are step -1
    // (read at iter 0 from buffer (0-1)&1 = 1).
    float cA[2][5], cB[2][5], hA[2][5], hB[2][5];
#pragma unroll
    for (int j = 0; j < 5; j++) {
        int u = u0 + j;
        cA[0][j] = c0[(size_t)b0 * HID + u];
        cA[1][j] = c0[(size_t)b1 * HID + u];
        cB[0][j] = c0[(size_t)B * HID + (size_t)b0 * HID + u];
        cB[1][j] = c0[(size_t)B * HID + (size_t)b1 * HID + u];
        sHA[1][e0][u] = h0[(size_t)b0 * HID + u];
        sHA[1][e1][u] = h0[(size_t)b1 * HID + u];
        sHB[1][e0][u] = h0[(size_t)B * HID + (size_t)b0 * HID + u];
        sHB[1][e1][u] = h0[(size_t)B * HID + (size_t)b1 * HID + u];
    }
    __syncthreads();

    float lg[2][3] = {{0.f, 0.f, 0.f}, {0.f, 0.f, 0.f}};
    const float2* x2 = reinterpret_cast<const float2*>(x);
    float2 xv0 = x2[b0];
    float2 xv1 = x2[b1];

    // L1(t): reads sHA[(t-1)&1], writes h1(t) -> sHA[t&1]
#define L1_BODY(t) do {                                                        \
        const int wb = (t) & 1, rb = wb ^ 1;                                   \
        ULL gpa[10], gpb[10];                                                  \
        const ulonglong2* bb = (const ulonglong2*)&sBias[0][sub][0];           \
        _Pragma("unroll")                                                      \
        for (int q = 0; q < 5; q++) {                                          \
            gpa[2 * q] = bb[q].x;  gpa[2 * q + 1] = bb[q].y;                   \
            gpb[2 * q] = bb[q].x;  gpb[2 * q + 1] = bb[q].y;                   \
        }                                                                      \
        mv_accum2(gpa, gpb, xv0.x, xv1.x, &sWx[0][sub][0]);                    \
        mv_accum2(gpa, gpb, xv0.y, xv1.y, &sWx[1][sub][0]);                    \
        _Pragma("unroll")                                                      \
        for (int k = 0; k < HID; k++)                                          \
            mv_accum2(gpa, gpb, sHA[rb][e0][k], sHA[rb][e1][k],                \
                      &sW[0][k][sub][0]);                                      \
        cell_update(gpa, cA[0], hA[0]);                                        \
        cell_update(gpb, cA[1], hA[1]);                                        \
        _Pragma("unroll")                                                      \
        for (int j = 0; j < 5; j++) {                                          \
            sHA[wb][e0][u0 + j] = hA[0][j];                                    \
            sHA[wb][e1][u0 + j] = hA[1][j];                                    \
        }                                                                      \
    } while (0)

    // L2(t): reads h1(t) from sHA[t&1], h2(t-1) from sHB[(t-1)&1];
    // writes h2(t) -> sHB[t&1]; accumulates decoder partials for step t.
#define L2_BODY(t) do {                                                        \
        const int hb = (t) & 1, rb2 = hb ^ 1;                                  \
        ULL g2a[10], g2b[10];                                                  \
        const ulonglong2* bb2 = (const ulonglong2*)&sBias[1][sub][0];          \
        _Pragma("unroll")                                                      \
        for (int q = 0; q < 5; q++) {                                          \
            g2a[2 * q] = bb2[q].x;  g2a[2 * q + 1] = bb2[q].y;                 \
            g2b[2 * q] = bb2[q].x;  g2b[2 * q + 1] = bb2[q].y;                 \
        }                                                                      \
        _Pragma("unroll")                                                      \
        for (int k = 0; k < HID; k++)                                          \
            mv_accum2(g2a, g2b, sHA[hb][e0][k], sHA[hb][e1][k],                \
                      &sW[1][k][sub][0]);                                      \
        _Pragma("unroll")                                                      \
        for (int k = 0; k < HID; k++)                                          \
            mv_accum2(g2a, g2b, sHB[rb2][e0][k], sHB[rb2][e1][k],              \
                      &sW[2][k][sub][0]);                                      \
        cell_update(g2a, cB[0], hB[0]);                                        \
        cell_update(g2b, cB[1], hB[1]);                                        \
        _Pragma("unroll")                                                      \
        for (int j = 0; j < 5; j++) {                                          \
            sHB[hb][e0][u0 + j] = hB[0][j];                                    \
            sHB[hb][e1][u0 + j] = hB[1][j];                                    \
        }                                                                      \
        const float* wd = Wdec + (t) * HID + u0;                               \
        _Pragma("unroll")                                                      \
        for (int j = 0; j < 5; j++) {                                          \
            float w0 = __ldg(wd + j);                                          \
            float w1 = __ldg(wd + T_STEPS * HID + j);                          \
            float w2 = __ldg(wd + 2 * T_STEPS * HID + j);                      \
            lg[0][0] = fmaf(hB[0][j], w0, lg[0][0]);                           \
            lg[0][1] = fmaf(hB[0][j], w1, lg[0][1]);                           \
            lg[0][2] = fmaf(hB[0][j], w2, lg[0][2]);                           \
            lg[1][0] = fmaf(hB[1][j], w0, lg[1][0]);                           \
            lg[1][1] = fmaf(hB[1][j], w1, lg[1][1]);                           \
            lg[1][2] = fmaf(hB[1][j], w2, lg[1][2]);                           \
        }                                                                      \
    } while (0)

    // ---- software pipeline: iter i does L1(i) + L2(i-1); ONE barrier/iter ----
    L1_BODY(0);
    xv0 = x2[(size_t)B + b0];
    xv1 = x2[(size_t)B + b1];
    __syncthreads();

#pragma unroll 1
    for (int i = 1; i < T_STEPS; i++) {
        L1_BODY(i);
        L2_BODY(i - 1);
        {
            int tn = (i + 1 < T_STEPS) ? (i + 1) : i;
            xv0 = x2[(size_t)tn * B + b0];
            xv1 = x2[(size_t)tn * B + b1];
        }
        __syncthreads();
    }
    L2_BODY(T_STEPS - 1);

    // ---------------- outputs ----------------
    float* o_h = out + 2 * (size_t)B;
    float* o_c = o_h + 2 * (size_t)B * HID;
#pragma unroll
    for (int j = 0; j < 5; j++) {
        int u = u0 + j;
        o_h[(size_t)b0 * HID + u]                   = hA[0][j];
        o_h[(size_t)b1 * HID + u]                   = hA[1][j];
        o_h[(size_t)B * HID + (size_t)b0 * HID + u] = hB[0][j];
        o_h[(size_t)B * HID + (size_t)b1 * HID + u] = hB[1][j];
        o_c[(size_t)b0 * HID + u]                   = cA[0][j];
        o_c[(size_t)b1 * HID + u]                   = cA[1][j];
        o_c[(size_t)B * HID + (size_t)b0 * HID + u] = cB[0][j];
        o_c[(size_t)B * HID + (size_t)b1 * HID + u] = cB[1][j];
    }

    // reduce decoder partials across the 4 warps
#pragma unroll
    for (int a = 0; a < 3; a++) {
        sLG[a][sub][e0] = lg[0][a];
        sLG[a][sub][e1] = lg[1][a];
    }
    __syncthreads();

    if (sub == 0) {
#pragma unroll
        for (int ei = 0; ei < 2; ei++) {
            int e = (ei == 0) ? e0 : e1;
            int b = (ei == 0) ? b0 : b1;
            float logit0 = sLG[0][0][e] + sLG[0][1][e] + sLG[0][2][e] + sLG[0][3][e] + bdec[0];
            float logit1 = sLG[1][0][e] + sLG[1][1][e] + sLG[1][2][e] + sLG[1][3][e] + bdec[1];
            float logit2 = sLG[2][0][e] + sLG[2][1][e] + sLG[2][2][e] + sLG[2][3][e] + bdec[2];

            float m   = fmaxf(logit0, fmaxf(logit1, logit2));
            float lse = m + logf(expf(logit0 - m) + expf(logit1 - m) + expf(logit2 - m));

            const float tinyf = 1.17549435e-38f;
            float best = -1e30f, sel_logit = logit0;
            int act = 0;
#pragma unroll
            for (int a = 0; a < 3; a++) {
                unsigned bits = jax_random_bits_partitionable((unsigned)(b * 3 + a));
                float f  = __uint_as_float((bits >> 9) | 0x3f800000u) - 1.0f;
                float uu = fmaxf(tinyf, f + tinyf);
                float gmb = -logf(-logf(uu));
                float lgv = (a == 0) ? logit0 : (a == 1) ? logit1 : logit2;
                float v   = lgv + gmb;
                if (v > best) { best = v; act = a; sel_logit = lgv; }
            }
            out[b]     = (float)act;
            out[B + b] = sel_logit - lse;
        }
    }
}

extern "C" void kernel_launch(void* const* d_in, const int* in_sizes, int n_in,
                              void* d_out, int out_size) {
    const float* x    = (const float*)d_in[0];
    const float* h0   = (const float*)d_in[1];
    const float* c0   = (const float*)d_in[2];
    const float* Wih0 = (const float*)d_in[3];
    const float* Whh0 = (const float*)d_in[4];
    const float* bih0 = (const float*)d_in[5];
    const float* bhh0 = (const float*)d_in[6];
    const float* Wih1 = (const float*)d_in[7];
    const float* Whh1 = (const float*)d_in[8];
    const float* bih1 = (const float*)d_in[9];
    const float* bhh1 = (const float*)d_in[10];
    const float* Wdec = (const float*)d_in[11];
    const float* bdec = (const float*)d_in[12];

    int B = in_sizes[0] / (T_STEPS * 2);   // x is [T, B, 2]
    dim3 grid(B / EPB), block(NTHR);
    lstm_fused_kernel<<<grid, block>>>(x, h0, c0, Wih0, Whh0, bih0, bhh0,
                                       Wih1, Whh1, bih1, bhh1, Wdec, bdec,
                                       (float*)d_out, B);
}

// round 17
// speedup vs baseline: 1.1562x; 1.0152x over previous
#include <cuda_runtime.h>
#include <cstdint>

#define T_STEPS 200
#define HID     20
#define NTHR    128      // 4 warps; warp = gate-quarter (sub), lane = element
#define EPB     64       // elements per block (2 per thread: lane, lane+32)
#define HPAD    21       // padded hidden stride (coprime with 32 -> conflict-free)

typedef unsigned long long ULL;

// ---------- packed f32x2 helpers (Blackwell FFMA2; PTX-only) ----------
#define FMA2(d, a, b, c) \
    asm("fma.rn.f32x2 %0, %1, %2, %3;" : "=l"(d) : "l"(a), "l"(b), "l"(c))

__device__ __forceinline__ ULL pack2(float x, float y) {
    ULL r;
    asm("mov.b64 %0, {%1, %2};" : "=l"(r)
        : "r"(__float_as_uint(x)), "r"(__float_as_uint(y)));
    return r;
}
__device__ __forceinline__ void unpack2(ULL v, float &x, float &y) {
    unsigned lo, hi;
    asm("mov.b64 {%0, %1}, %2;" : "=r"(lo), "=r"(hi) : "l"(v));
    x = __uint_as_float(lo);
    y = __uint_as_float(hi);
}

// ---------- fast activations (MUFU EX2+RCP, ~1e-6 rel err) ----------
__device__ __forceinline__ float sigm(float x) {
    return __fdividef(1.0f, 1.0f + __expf(-x));
}
__device__ __forceinline__ float tanh_fast(float x) {
    float ax = fabsf(x);
    float e  = __expf(-2.0f * ax);
    float r  = __fdividef(1.0f - e, 1.0f + e);
    return copysignf(r, x);
}

// one LSTM unit update — EXACT same expression/order as cell_update
__device__ __forceinline__ void cell_unit(float iv, float fv, float gv, float ov,
                                          float &c, float &h) {
    float cv = fmaf(sigm(fv), c, sigm(iv) * tanh_fast(gv));
    c = cv;
    h = sigm(ov) * tanh_fast(cv);
}

// ---------- exact JAX threefry2x32 (20 rounds) ----------
__device__ __forceinline__ void threefry2x32(unsigned k0, unsigned k1,
                                             unsigned x0, unsigned x1,
                                             unsigned &o0, unsigned &o1) {
    unsigned ks2 = k0 ^ k1 ^ 0x1BD11BDAu;
    x0 += k0; x1 += k1;
#define TFR(r) { x0 += x1; x1 = (x1 << r) | (x1 >> (32 - r)); x1 ^= x0; }
    TFR(13) TFR(15) TFR(26) TFR(6)
    x0 += k1;  x1 += ks2 + 1u;
    TFR(17) TFR(29) TFR(16) TFR(24)
    x0 += ks2; x1 += k0 + 2u;
    TFR(13) TFR(15) TFR(26) TFR(6)
    x0 += k0;  x1 += k1 + 3u;
    TFR(17) TFR(29) TFR(16) TFR(24)
    x0 += k1;  x1 += ks2 + 4u;
    TFR(13) TFR(15) TFR(26) TFR(6)
    x0 += ks2; x1 += k0 + 5u;
#undef TFR
    o0 = x0; o1 = x1;
}
// JAX partitionable threefry: ctr=(0,j), bits = o0^o1  (key (0,42))
__device__ __forceinline__ unsigned jax_random_bits_partitionable(unsigned j) {
    unsigned o0, o1;
    threefry2x32(0u, 42u, 0u, j, o0, o1);
    return o0 ^ o1;
}

// One k-contribution for two elements: 5 broadcast LDS.128 -> 20 FFMA2.
__device__ __forceinline__ void mv_accum2(ULL* gpa, ULL* gpb,
                                          float ha, float hb,
                                          const float4* __restrict__ wrow) {
    ULL h2a = pack2(ha, ha);
    ULL h2b = pack2(hb, hb);
    const ulonglong2* r = reinterpret_cast<const ulonglong2*>(wrow);
#pragma unroll
    for (int q = 0; q < 5; q++) {
        ulonglong2 w = r[q];
        FMA2(gpa[2 * q],     h2a, w.x, gpa[2 * q]);
        FMA2(gpa[2 * q + 1], h2a, w.y, gpa[2 * q + 1]);
        FMA2(gpb[2 * q],     h2b, w.x, gpb[2 * q]);
        FMA2(gpb[2 * q + 1], h2b, w.y, gpb[2 * q + 1]);
    }
}

// gp layout (units u0..u0+4): gp[2q],gp[2q+1] (q<4) = gate-group q for units
// (u0..u0+3); gp[8]=(i4,f4), gp[9]=(g4,o4) for unit u0+4
__device__ __forceinline__ void cell_update(ULL* gp, float* c, float* hout) {
    float iv[5], fv[5], gv[5], ov[5];
    unpack2(gp[0], iv[0], iv[1]); unpack2(gp[1], iv[2], iv[3]);
    unpack2(gp[2], fv[0], fv[1]); unpack2(gp[3], fv[2], fv[3]);
    unpack2(gp[4], gv[0], gv[1]); unpack2(gp[5], gv[2], gv[3]);
    unpack2(gp[6], ov[0], ov[1]); unpack2(gp[7], ov[2], ov[3]);
    unpack2(gp[8], iv[4], fv[4]);
    unpack2(gp[9], gv[4], ov[4]);
#pragma unroll
    for (int j = 0; j < 5; j++)
        cell_unit(iv[j], fv[j], gv[j], ov[j], c[j], hout[j]);
}

// unpack a gate accumulator set into per-unit scalar arrays (ALU only)
__device__ __forceinline__ void unpack_gates(const ULL* gp, float* iv, float* fv,
                                             float* gv, float* ov) {
    unpack2(gp[0], iv[0], iv[1]); unpack2(gp[1], iv[2], iv[3]);
    unpack2(gp[2], fv[0], fv[1]); unpack2(gp[3], fv[2], fv[3]);
    unpack2(gp[4], gv[0], gv[1]); unpack2(gp[5], gv[2], gv[3]);
    unpack2(gp[6], ov[0], ov[1]); unpack2(gp[7], ov[2], ov[3]);
    unpack2(gp[8], iv[4], fv[4]);
    unpack2(gp[9], gv[4], ov[4]);
}

__global__ void __launch_bounds__(NTHR, 2)
lstm_fused_kernel(const float* __restrict__ x,
                  const float* __restrict__ h0,
                  const float* __restrict__ c0,
                  const float* __restrict__ Wih0,
                  const float* __restrict__ Whh0,
                  const float* __restrict__ bih0,
                  const float* __restrict__ bhh0,
                  const float* __restrict__ Wih1,
                  const float* __restrict__ Whh1,
                  const float* __restrict__ bih1,
                  const float* __restrict__ bhh1,
                  const float* __restrict__ Wdec,
                  const float* __restrict__ bdec,
                  float* __restrict__ out,
                  int B) {
    // sW[m][k][sub][q]: m=0 Whh0, m=1 Wih1, m=2 Whh1 (gate-permuted float4 packs)
    __shared__ float4 sW[3][HID][4][5];
    __shared__ float4 sWx[2][4][5];        // Wih0 columns 0/1
    __shared__ float4 sBias[2][4][5];      // combined biases per layer
    __shared__ float  sHA[2][EPB][HPAD];   // double-buffered layer-1 h (scalar)
    __shared__ float  sHB[2][EPB][HPAD];   // double-buffered layer-2 h (scalar)
    __shared__ float  sLG[3][4][EPB];      // decoder partial reduction scratch

    const int tid = threadIdx.x;
    const int sub = tid >> 5;           // warp id = gate quarter
    const int e0  = tid & 31;           // lane = first element
    const int e1  = e0 + 32;            // second element
    const int b0  = blockIdx.x * EPB + e0;
    const int b1  = b0 + 32;
    const int u0  = 5 * sub;

    // ---------------- stage weights ----------------
    {
        const float* Wsrc[3] = {Whh0, Wih1, Whh1};
        for (int idx = tid; idx < 3 * HID * 4 * 5; idx += NTHR) {
            int m = idx / (HID * 20);
            int r = idx % (HID * 20);
            int k = r / 20;
            int s = (r % 20) / 5;
            int q = r % 5;
            const float* W = Wsrc[m];
            float4 v;
            if (q < 4) {
                int g = 20 * q + 5 * s;
                v = make_float4(W[(g + 0) * HID + k], W[(g + 1) * HID + k],
                                W[(g + 2) * HID + k], W[(g + 3) * HID + k]);
            } else {
                int u = 5 * s + 4;
                v = make_float4(W[u * HID + k],        W[(20 + u) * HID + k],
                                W[(40 + u) * HID + k], W[(60 + u) * HID + k]);
            }
            sW[m][k][s][q] = v;
        }
        for (int idx = tid; idx < 2 * 4 * 5; idx += NTHR) {
            int i = idx / 20, s = (idx % 20) / 5, q = idx % 5;
            float4 v;
            if (q < 4) {
                int g = 20 * q + 5 * s;
                v = make_float4(Wih0[(g + 0) * 2 + i], Wih0[(g + 1) * 2 + i],
                                Wih0[(g + 2) * 2 + i], Wih0[(g + 3) * 2 + i]);
            } else {
                int u = 5 * s + 4;
                v = make_float4(Wih0[u * 2 + i],        Wih0[(20 + u) * 2 + i],
                                Wih0[(40 + u) * 2 + i], Wih0[(60 + u) * 2 + i]);
            }
            sWx[i][s][q] = v;
        }
        for (int idx = tid; idx < 2 * 4 * 5; idx += NTHR) {
            int l = idx / 20, s = (idx % 20) / 5, q = idx % 5;
            const float* bi = l ? bih1 : bih0;
            const float* bh = l ? bhh1 : bhh0;
            float4 v;
            if (q < 4) {
                int g = 20 * q + 5 * s;
                v = make_float4(bi[g] + bh[g],         bi[g + 1] + bh[g + 1],
                                bi[g + 2] + bh[g + 2], bi[g + 3] + bh[g + 3]);
            } else {
                int u = 5 * s + 4;
                v = make_float4(bi[u] + bh[u],           bi[20 + u] + bh[20 + u],
                                bi[40 + u] + bh[40 + u], bi[60 + u] + bh[60 + u]);
            }
            sBias[l][s][q] = v;
        }
    }

    // ---------------- init state ----------------
    float cA[2][5], cB[2][5], hA[2][5], hB[2][5];
#pragma unroll
    for (int j = 0; j < 5; j++) {
        int u = u0 + j;
        cA[0][j] = c0[(size_t)b0 * HID + u];
        cA[1][j] = c0[(size_t)b1 * HID + u];
        cB[0][j] = c0[(size_t)B * HID + (size_t)b0 * HID + u];
        cB[1][j] = c0[(size_t)B * HID + (size_t)b1 * HID + u];
        sHA[1][e0][u] = h0[(size_t)b0 * HID + u];
        sHA[1][e1][u] = h0[(size_t)b1 * HID + u];
        sHB[1][e0][u] = h0[(size_t)B * HID + (size_t)b0 * HID + u];
        sHB[1][e1][u] = h0[(size_t)B * HID + (size_t)b1 * HID + u];
    }
    __syncthreads();

    float lg[2][3] = {{0.f, 0.f, 0.f}, {0.f, 0.f, 0.f}};
    const float2* x2 = reinterpret_cast<const float2*>(x);
    float2 xv0 = x2[b0];
    float2 xv1 = x2[b1];

    // ---------------- prologue: L1(0) ----------------
    {
        ULL gpa[10], gpb[10];
        const ulonglong2* bb = (const ulonglong2*)&sBias[0][sub][0];
#pragma unroll
        for (int q = 0; q < 5; q++) {
            gpa[2 * q] = bb[q].x;  gpa[2 * q + 1] = bb[q].y;
            gpb[2 * q] = bb[q].x;  gpb[2 * q + 1] = bb[q].y;
        }
        mv_accum2(gpa, gpb, xv0.x, xv1.x, &sWx[0][sub][0]);
        mv_accum2(gpa, gpb, xv0.y, xv1.y, &sWx[1][sub][0]);
#pragma unroll
        for (int k = 0; k < HID; k++)
            mv_accum2(gpa, gpb, sHA[1][e0][k], sHA[1][e1][k], &sW[0][k][sub][0]);
        cell_update(gpa, cA[0], hA[0]);
        cell_update(gpb, cA[1], hA[1]);
#pragma unroll
        for (int j = 0; j < 5; j++) {
            sHA[0][e0][u0 + j] = hA[0][j];
            sHA[0][e1][u0 + j] = hA[1][j];
        }
    }
    xv0 = x2[(size_t)B + b0];
    xv1 = x2[(size_t)B + b1];
    __syncthreads();

    // ---------------- main loop: iter i = L2(i-1) + L1(i), 1 barrier ----------------
#pragma unroll 1
    for (int i = 1; i < T_STEPS; i++) {
        const int hb  = (i - 1) & 1;   // buffer holding h1(i-1); L2 writes h2(i-1) here
        const int rb2 = hb ^ 1;        // buffer holding h2(i-2)
        const int wb  = i & 1;         // L1 writes h1(i) here (== rb2)

        // ---- L2(i-1) matvec ----
        ULL g2a[10], g2b[10];
        {
            const ulonglong2* bb2 = (const ulonglong2*)&sBias[1][sub][0];
#pragma unroll
            for (int q = 0; q < 5; q++) {
                g2a[2 * q] = bb2[q].x;  g2a[2 * q + 1] = bb2[q].y;
                g2b[2 * q] = bb2[q].x;  g2b[2 * q + 1] = bb2[q].y;
            }
#pragma unroll
            for (int k = 0; k < HID; k++)
                mv_accum2(g2a, g2b, sHA[hb][e0][k], sHA[hb][e1][k],
                          &sW[1][k][sub][0]);
#pragma unroll
            for (int k = 0; k < HID; k++)
                mv_accum2(g2a, g2b, sHB[rb2][e0][k], sHB[rb2][e1][k],
                          &sW[2][k][sub][0]);
        }
        // unpack L2 gates to scalars (ALU only; frees g2 registers)
        float IV[2][5], FV[2][5], GV[2][5], OV[2][5];
        unpack_gates(g2a, IV[0], FV[0], GV[0], OV[0]);
        unpack_gates(g2b, IV[1], FV[1], GV[1], OV[1]);

        // ---- L1(i) matvec init: bias + input projection ----
        ULL gpa[10], gpb[10];
        {
            const ulonglong2* bb = (const ulonglong2*)&sBias[0][sub][0];
#pragma unroll
            for (int q = 0; q < 5; q++) {
                gpa[2 * q] = bb[q].x;  gpa[2 * q + 1] = bb[q].y;
                gpb[2 * q] = bb[q].x;  gpb[2 * q + 1] = bb[q].y;
            }
        }
        mv_accum2(gpa, gpb, xv0.x, xv1.x, &sWx[0][sub][0]);
        mv_accum2(gpa, gpb, xv0.y, xv1.y, &sWx[1][sub][0]);

        // ---- INTERLEAVE: 5 chunks of (4 L1-matvec k-iters + 1 L2 cell unit) ----
        // FFMA2 bursts fill issue slots while the MUFU chains of cell_unit pend.
#pragma unroll
        for (int ch = 0; ch < 5; ch++) {
#pragma unroll
            for (int kk = 0; kk < 4; kk++) {
                int k = 4 * ch + kk;
                mv_accum2(gpa, gpb, sHA[hb][e0][k], sHA[hb][e1][k],
                          &sW[0][k][sub][0]);
            }
            cell_unit(IV[0][ch], FV[0][ch], GV[0][ch], OV[0][ch],
                      cB[0][ch], hB[0][ch]);
            cell_unit(IV[1][ch], FV[1][ch], GV[1][ch], OV[1][ch],
                      cB[1][ch], hB[1][ch]);
        }

        // ---- h2(i-1) stores + decoder partials ----
#pragma unroll
        for (int j = 0; j < 5; j++) {
            sHB[hb][e0][u0 + j] = hB[0][j];
            sHB[hb][e1][u0 + j] = hB[1][j];
        }
        {
            const float* wd = Wdec + (i - 1) * HID + u0;
#pragma unroll
            for (int j = 0; j < 5; j++) {
                float w0 = __ldg(wd + j);
                float w1 = __ldg(wd + T_STEPS * HID + j);
                float w2 = __ldg(wd + 2 * T_STEPS * HID + j);
                lg[0][0] = fmaf(hB[0][j], w0, lg[0][0]);
                lg[0][1] = fmaf(hB[0][j], w1, lg[0][1]);
                lg[0][2] = fmaf(hB[0][j], w2, lg[0][2]);
                lg[1][0] = fmaf(hB[1][j], w0, lg[1][0]);
                lg[1][1] = fmaf(hB[1][j], w1, lg[1][1]);
                lg[1][2] = fmaf(hB[1][j], w2, lg[1][2]);
            }
        }

        // ---- L1(i) cell update + h1(i) stores ----
        cell_update(gpa, cA[0], hA[0]);
        cell_update(gpb, cA[1], hA[1]);
#pragma unroll
        for (int j = 0; j < 5; j++) {
            sHA[wb][e0][u0 + j] = hA[0][j];
            sHA[wb][e1][u0 + j] = hA[1][j];
        }

        // ---- x prefetch for next step ----
        {
            int tn = (i + 1 < T_STEPS) ? (i + 1) : i;
            xv0 = x2[(size_t)tn * B + b0];
            xv1 = x2[(size_t)tn * B + b1];
        }
        __syncthreads();
    }

    // ---------------- epilogue: L2(T-1) ----------------
    {
        const int hb  = (T_STEPS - 1) & 1;   // h1(T-1) buffer
        const int rb2 = hb ^ 1;              // h2(T-2) buffer
        ULL g2a[10], g2b[10];
        const ulonglong2* bb2 = (const ulonglong2*)&sBias[1][sub][0];
#pragma unroll
        for (int q = 0; q < 5; q++) {
            g2a[2 * q] = bb2[q].x;  g2a[2 * q + 1] = bb2[q].y;
            g2b[2 * q] = bb2[q].x;  g2b[2 * q + 1] = bb2[q].y;
        }
#pragma unroll
        for (int k = 0; k < HID; k++)
            mv_accum2(g2a, g2b, sHA[hb][e0][k], sHA[hb][e1][k], &sW[1][k][sub][0]);
#pragma unroll
        for (int k = 0; k < HID; k++)
            mv_accum2(g2a, g2b, sHB[rb2][e0][k], sHB[rb2][e1][k], &sW[2][k][sub][0]);
        cell_update(g2a, cB[0], hB[0]);
        cell_update(g2b, cB[1], hB[1]);
        const float* wd = Wdec + (T_STEPS - 1) * HID + u0;
#pragma unroll
        for (int j = 0; j < 5; j++) {
            float w0 = __ldg(wd + j);
            float w1 = __ldg(wd + T_STEPS * HID + j);
            float w2 = __ldg(wd + 2 * T_STEPS * HID + j);
            lg[0][0] = fmaf(hB[0][j], w0, lg[0][0]);
            lg[0][1] = fmaf(hB[0][j], w1, lg[0][1]);
            lg[0][2] = fmaf(hB[0][j], w2, lg[0][2]);
            lg[1][0] = fmaf(hB[1][j], w0, lg[1][0]);
            lg[1][1] = fmaf(hB[1][j], w1, lg[1][1]);
            lg[1][2] = fmaf(hB[1][j], w2, lg[1][2]);
        }
    }

    // ---------------- outputs ----------------
    float* o_h = out + 2 * (size_t)B;
    float* o_c = o_h + 2 * (size_t)B * HID;
#pragma unroll
    for (int j = 0; j < 5; j++) {
        int u = u0 + j;
        o_h[(size_t)b0 * HID + u]                   = hA[0][j];
        o_h[(size_t)b1 * HID + u]                   = hA[1][j];
        o_h[(size_t)B * HID + (size_t)b0 * HID + u] = hB[0][j];
        o_h[(size_t)B * HID + (size_t)b1 * HID + u] = hB[1][j];
        o_c[(size_t)b0 * HID + u]                   = cA[0][j];
        o_c[(size_t)b1 * HID + u]                   = cA[1][j];
        o_c[(size_t)B * HID + (size_t)b0 * HID + u] = cB[0][j];
        o_c[(size_t)B * HID + (size_t)b1 * HID + u] = cB[1][j];
    }

    // reduce decoder partials across the 4 warps
#pragma unroll
    for (int a = 0; a < 3; a++) {
        sLG[a][sub][e0] = lg[0][a];
        sLG[a][sub][e1] = lg[1][a];
    }
    __syncthreads();

    if (sub == 0) {
#pragma unroll
        for (int ei = 0; ei < 2; ei++) {
            int e = (ei == 0) ? e0 : e1;
            int b = (ei == 0) ? b0 : b1;
            float logit0 = sLG[0][0][e] + sLG[0][1][e] + sLG[0][2][e] + sLG[0][3][e] + bdec[0];
            float logit1 = sLG[1][0][e] + sLG[1][1][e] + sLG[1][2][e] + sLG[1][3][e] + bdec[1];
            float logit2 = sLG[2][0][e] + sLG[2][1][e] + sLG[2][2][e] + sLG[2][3][e] + bdec[2];

            float m   = fmaxf(logit0, fmaxf(logit1, logit2));
            float lse = m + logf(expf(logit0 - m) + expf(logit1 - m) + expf(logit2 - m));

            const float tinyf = 1.17549435e-38f;
            float best = -1e30f, sel_logit = logit0;
            int act = 0;
#pragma unroll
            for (int a = 0; a < 3; a++) {
                unsigned bits = jax_random_bits_partitionable((unsigned)(b * 3 + a));
                float f  = __uint_as_float((bits >> 9) | 0x3f800000u) - 1.0f;
                float uu = fmaxf(tinyf, f + tinyf);
                float gmb = -logf(-logf(uu));
                float lgv = (a == 0) ? logit0 : (a == 1) ? logit1 : logit2;
                float v   = lgv + gmb;
                if (v > best) { best = v; act = a; sel_logit = lgv; }
            }
            out[b]     = (float)act;
            out[B + b] = sel_logit - lse;
        }
    }
}

extern "C" void kernel_launch(void* const* d_in, const int* in_sizes, int n_in,
                              void* d_out, int out_size) {
    const float* x    = (const float*)d_in[0];
    const float* h0   = (const float*)d_in[1];
    const float* c0   = (const float*)d_in[2];
    const float* Wih0 = (const float*)d_in[3];
    const float* Whh0 = (const float*)d_in[4];
    const float* bih0 = (const float*)d_in[5];
    const float* bhh0 = (const float*)d_in[6];
    const float* Wih1 = (const float*)d_in[7];
    const float* Whh1 = (const float*)d_in[8];
    const float* bih1 = (const float*)d_in[9];
    const float* bhh1 = (const float*)d_in[10];
    const float* Wdec = (const float*)d_in[11];
    const float* bdec = (const float*)d_in[12];

    int B = in_sizes[0] / (T_STEPS * 2);   // x is [T, B, 2]
    dim3 grid(B / EPB), block(NTHR);
    lstm_fused_kernel<<<grid, block>>>(x, h0, c0, Wih0, Whh0, bih0, bhh0,
                                       Wih1, Whh1, bih1, bhh1, Wdec, bdec,
                                       (float*)d_out, B);
}